// round 4
// baseline (speedup 1.0000x reference)
#include <cuda_runtime.h>
#include <math_constants.h>

// SpatialAttention: out = x * hardsigmoid(conv3x3([mean_c(x); max_c(x)]))
// x: [16, 256, 128, 128] fp32, conv_w: [1, 2, 3, 3] fp32.
//
// Fused pipelined kernel, 2-batch chunks:
//   launch i:  reduce(chunk i) | conv(chunk i-1) | mul(chunk i-2)
// reduce warms L2 with x slice; mul (2 launches later) consumes it from L2
// with __ldcs (evict-first on last use) and streams output with __stcs.

#define BATCH 16
#define CH    256
#define HH    128
#define WW    128
#define HWSZ  (HH * WW)          // 16384
#define HW4   (HWSZ / 4)         // 4096 float4 cols per (b,c) plane
#define CHUNK 2                  // batches per chunk (32 MiB x-slice)
#define NCHNK (BATCH / CHUNK)    // 8 chunks
#define CPS   32                 // channels per channel-group (256/8)

#define COLS_PER_BLK 32
#define MVEC  4                                        // float4s per mul thread
#define R_BLK (CHUNK * HW4 / COLS_PER_BLK)             // 256 reduce blocks
#define C_BLK (CHUNK * HWSZ / 256)                     // 128 conv blocks
#define M_BLK (CHUNK * CH * HW4 / (256 * MVEC))        // 2048 mul blocks

__device__ float g_avg[BATCH * HWSZ];
__device__ float g_max[BATCH * HWSZ];
__device__ float g_att[BATCH * HWSZ];

__global__ void __launch_bounds__(256, 6)
fused_kernel(const float* __restrict__ x, const float* __restrict__ wt,
             float* __restrict__ out, int b_red, int b_conv, int b_mul) {
    __shared__ float4 ssum[256];
    __shared__ float4 smax[256];

    int bid = blockIdx.x;

    if (bid < R_BLK) {
        // ---------------- reduce phase: chunk b_red ----------------
        if (b_red < 0) return;
        int bl      = bid >> 7;                 // / 128
        int colBase = (bid & 127) * COLS_PER_BLK;
        int t     = threadIdx.x;
        int col_l = t & (COLS_PER_BLK - 1);
        int cg    = t >> 5;                     // 0..7 channel group
        int b     = b_red + bl;

        const float4* xp = reinterpret_cast<const float4*>(x)
                         + (size_t)b * CH * HW4 + (size_t)cg * CPS * HW4
                         + colBase + col_l;

        float4 s = make_float4(0.f, 0.f, 0.f, 0.f);
        float4 m = make_float4(-CUDART_INF_F, -CUDART_INF_F, -CUDART_INF_F, -CUDART_INF_F);

        #pragma unroll 8
        for (int c = 0; c < CPS; c++) {
            float4 v = xp[c * HW4];
            s.x += v.x; s.y += v.y; s.z += v.z; s.w += v.w;
            m.x = fmaxf(m.x, v.x); m.y = fmaxf(m.y, v.y);
            m.z = fmaxf(m.z, v.z); m.w = fmaxf(m.w, v.w);
        }
        ssum[t] = s; smax[t] = m;
        __syncthreads();

        #pragma unroll
        for (int off = 128; off >= 32; off >>= 1) {
            if (t < off) {
                float4 s2 = ssum[t + off], m2 = smax[t + off];
                float4 sa = ssum[t],       ma = smax[t];
                sa.x += s2.x; sa.y += s2.y; sa.z += s2.z; sa.w += s2.w;
                ma.x = fmaxf(ma.x, m2.x); ma.y = fmaxf(ma.y, m2.y);
                ma.z = fmaxf(ma.z, m2.z); ma.w = fmaxf(ma.w, m2.w);
                ssum[t] = sa; smax[t] = ma;
            }
            __syncthreads();
        }

        if (t < COLS_PER_BLK) {
            const float inv = 1.0f / (float)CH;
            float4 sa = ssum[t], ma = smax[t];
            float4 a = make_float4(sa.x * inv, sa.y * inv, sa.z * inv, sa.w * inv);
            reinterpret_cast<float4*>(g_avg)[b * HW4 + colBase + t] = a;
            reinterpret_cast<float4*>(g_max)[b * HW4 + colBase + t] = ma;
        }
    } else if (bid < R_BLK + C_BLK) {
        // ---------------- conv phase: chunk b_conv ----------------
        if (b_conv < 0) return;
        int t  = (bid - R_BLK) * 256 + threadIdx.x;   // 0 .. CHUNK*HWSZ-1
        int bl = t >> 14;
        int hw = t & (HWSZ - 1);
        int h  = hw >> 7;
        int w  = hw & (WW - 1);
        int b  = b_conv + bl;

        const float* __restrict__ A = g_avg + b * HWSZ;
        const float* __restrict__ M = g_max + b * HWSZ;

        float acc = 0.f;
        #pragma unroll
        for (int kh = 0; kh < 3; kh++) {
            int hh = h + kh - 1;
            if (hh < 0 || hh >= HH) continue;
            #pragma unroll
            for (int kw = 0; kw < 3; kw++) {
                int ww = w + kw - 1;
                if (ww < 0 || ww >= WW) continue;
                int o = hh * WW + ww;
                acc += __ldg(&wt[kh * 3 + kw])     * A[o]
                     + __ldg(&wt[9 + kh * 3 + kw]) * M[o];
            }
        }
        float y = fminf(fmaxf(acc + 3.0f, 0.0f), 6.0f) * (1.0f / 6.0f);
        g_att[b * HWSZ + hw] = y;
    } else {
        // ---------------- mul phase: chunk b_mul (MVEC float4/thread) -------
        if (b_mul < 0) return;
        int t    = (bid - R_BLK - C_BLK) * 256 + threadIdx.x;
        int base = t * MVEC;                          // float4 index in chunk
        int bl   = base >> 20;                        // / (CH*HW4)
        int rem  = base & ((CH * HW4) - 1);
        int col  = rem & (HW4 - 1);                   // aligned: col..col+3 in-plane
        int b    = b_mul + bl;

        size_t gidx = (size_t)b * CH * HW4 + rem;
        const float4* xp = reinterpret_cast<const float4*>(x) + gidx;
        const float4* ap = reinterpret_cast<const float4*>(g_att) + (size_t)b * HW4 + col;
        float4*       op = reinterpret_cast<float4*>(out) + gidx;

        float4 v[MVEC], a[MVEC];
        #pragma unroll
        for (int j = 0; j < MVEC; j++) v[j] = __ldcs(xp + j);
        #pragma unroll
        for (int j = 0; j < MVEC; j++) a[j] = __ldg(ap + j);
        #pragma unroll
        for (int j = 0; j < MVEC; j++) {
            v[j].x *= a[j].x; v[j].y *= a[j].y;
            v[j].z *= a[j].z; v[j].w *= a[j].w;
            __stcs(op + j, v[j]);
        }
    }
}

extern "C" void kernel_launch(void* const* d_in, const int* in_sizes, int n_in,
                              void* d_out, int out_size) {
    const float* x  = (const float*)d_in[0];
    const float* wt = (const float*)d_in[1];
    float* out      = (float*)d_out;

    const int GRID = R_BLK + C_BLK + M_BLK;   // 2432 blocks

    for (int i = 0; i < NCHNK + 2; i++) {
        int br = (i < NCHNK)              ? i * CHUNK       : -1;
        int bc = (i >= 1 && i <= NCHNK)   ? (i - 1) * CHUNK : -1;
        int bm = (i >= 2)                 ? (i - 2) * CHUNK : -1;
        fused_kernel<<<GRID, 256>>>(x, wt, out, br, bc, bm);
    }
}

// round 5
// speedup vs baseline: 1.1804x; 1.1804x over previous
#include <cuda_runtime.h>
#include <math_constants.h>

// SpatialAttention: out = x * hardsigmoid(conv3x3([mean_c(x); max_c(x)]))
// x: [16, 256, 128, 128] fp32, conv_w: [1, 2, 3, 3] fp32.
//
// Fused pipelined kernel, 2-batch chunks:
//   launch i:  reduce(chunk i) | conv(chunk i-1) | mul(chunk i-2)
// mul: 4 float4/thread strided WARP-CONTIGUOUSLY by the phase width
// (R4's thread-contiguous stride caused an 8x L1tex wavefront blowup).

#define BATCH 16
#define CH    256
#define HH    128
#define WW    128
#define HWSZ  (HH * WW)          // 16384
#define HW4   (HWSZ / 4)         // 4096 float4 cols per (b,c) plane
#define CHUNK 2                  // batches per chunk (32 MiB x-slice)
#define NCHNK (BATCH / CHUNK)    // 8 chunks
#define CPS   32                 // channels per channel-group (256/8)

#define COLS_PER_BLK 32
#define MVEC  4                                        // float4s per mul thread
#define R_BLK (CHUNK * HW4 / COLS_PER_BLK)             // 256 reduce blocks
#define C_BLK (CHUNK * HWSZ / 256)                     // 128 conv blocks
#define M_THREADS (CHUNK * CH * HW4 / MVEC)            // 524288 mul threads
#define M_BLK (M_THREADS / 256)                        // 2048 mul blocks

__device__ float g_avg[BATCH * HWSZ];
__device__ float g_max[BATCH * HWSZ];
__device__ float g_att[BATCH * HWSZ];

__global__ void __launch_bounds__(256, 6)
fused_kernel(const float* __restrict__ x, const float* __restrict__ wt,
             float* __restrict__ out, int b_red, int b_conv, int b_mul) {
    __shared__ float4 ssum[256];
    __shared__ float4 smax[256];

    int bid = blockIdx.x;

    if (bid < R_BLK) {
        // ---------------- reduce phase: chunk b_red ----------------
        if (b_red < 0) return;
        int bl      = bid >> 7;                 // / 128
        int colBase = (bid & 127) * COLS_PER_BLK;
        int t     = threadIdx.x;
        int col_l = t & (COLS_PER_BLK - 1);
        int cg    = t >> 5;                     // 0..7 channel group
        int b     = b_red + bl;

        const float4* xp = reinterpret_cast<const float4*>(x)
                         + (size_t)b * CH * HW4 + (size_t)cg * CPS * HW4
                         + colBase + col_l;

        float4 s = make_float4(0.f, 0.f, 0.f, 0.f);
        float4 m = make_float4(-CUDART_INF_F, -CUDART_INF_F, -CUDART_INF_F, -CUDART_INF_F);

        #pragma unroll 8
        for (int c = 0; c < CPS; c++) {
            float4 v = xp[c * HW4];
            s.x += v.x; s.y += v.y; s.z += v.z; s.w += v.w;
            m.x = fmaxf(m.x, v.x); m.y = fmaxf(m.y, v.y);
            m.z = fmaxf(m.z, v.z); m.w = fmaxf(m.w, v.w);
        }
        ssum[t] = s; smax[t] = m;
        __syncthreads();

        #pragma unroll
        for (int off = 128; off >= 32; off >>= 1) {
            if (t < off) {
                float4 s2 = ssum[t + off], m2 = smax[t + off];
                float4 sa = ssum[t],       ma = smax[t];
                sa.x += s2.x; sa.y += s2.y; sa.z += s2.z; sa.w += s2.w;
                ma.x = fmaxf(ma.x, m2.x); ma.y = fmaxf(ma.y, m2.y);
                ma.z = fmaxf(ma.z, m2.z); ma.w = fmaxf(ma.w, m2.w);
                ssum[t] = sa; smax[t] = ma;
            }
            __syncthreads();
        }

        if (t < COLS_PER_BLK) {
            const float inv = 1.0f / (float)CH;
            float4 sa = ssum[t], ma = smax[t];
            float4 a = make_float4(sa.x * inv, sa.y * inv, sa.z * inv, sa.w * inv);
            reinterpret_cast<float4*>(g_avg)[b * HW4 + colBase + t] = a;
            reinterpret_cast<float4*>(g_max)[b * HW4 + colBase + t] = ma;
        }
    } else if (bid < R_BLK + C_BLK) {
        // ---------------- conv phase: chunk b_conv ----------------
        if (b_conv < 0) return;
        int t  = (bid - R_BLK) * 256 + threadIdx.x;   // 0 .. CHUNK*HWSZ-1
        int bl = t >> 14;
        int hw = t & (HWSZ - 1);
        int h  = hw >> 7;
        int w  = hw & (WW - 1);
        int b  = b_conv + bl;

        const float* __restrict__ A = g_avg + b * HWSZ;
        const float* __restrict__ M = g_max + b * HWSZ;

        float acc = 0.f;
        #pragma unroll
        for (int kh = 0; kh < 3; kh++) {
            int hh = h + kh - 1;
            if (hh < 0 || hh >= HH) continue;
            #pragma unroll
            for (int kw = 0; kw < 3; kw++) {
                int ww = w + kw - 1;
                if (ww < 0 || ww >= WW) continue;
                int o = hh * WW + ww;
                acc += __ldg(&wt[kh * 3 + kw])     * A[o]
                     + __ldg(&wt[9 + kh * 3 + kw]) * M[o];
            }
        }
        float y = fminf(fmaxf(acc + 3.0f, 0.0f), 6.0f) * (1.0f / 6.0f);
        g_att[b * HWSZ + hw] = y;
    } else {
        // ------- mul phase: chunk b_mul, warp-contiguous MVEC striding ------
        if (b_mul < 0) return;
        int t = (bid - R_BLK - C_BLK) * 256 + threadIdx.x;  // 0 .. M_THREADS-1

        const float4* xbase = reinterpret_cast<const float4*>(x)
                            + (size_t)b_mul * CH * HW4;
        float4*       obase = reinterpret_cast<float4*>(out)
                            + (size_t)b_mul * CH * HW4;
        const float4* abase = reinterpret_cast<const float4*>(g_att);

        float4 v[MVEC], a[MVEC];
        #pragma unroll
        for (int j = 0; j < MVEC; j++) {
            int idx = t + j * M_THREADS;        // float4 index within chunk
            v[j] = __ldcs(xbase + idx);
        }
        #pragma unroll
        for (int j = 0; j < MVEC; j++) {
            int idx = t + j * M_THREADS;
            int bl  = idx >> 20;                // / (CH*HW4)
            int col = idx & (HW4 - 1);
            a[j] = __ldg(abase + (size_t)(b_mul + bl) * HW4 + col);
        }
        #pragma unroll
        for (int j = 0; j < MVEC; j++) {
            int idx = t + j * M_THREADS;
            v[j].x *= a[j].x; v[j].y *= a[j].y;
            v[j].z *= a[j].z; v[j].w *= a[j].w;
            __stcs(obase + idx, v[j]);
        }
    }
}

extern "C" void kernel_launch(void* const* d_in, const int* in_sizes, int n_in,
                              void* d_out, int out_size) {
    const float* x  = (const float*)d_in[0];
    const float* wt = (const float*)d_in[1];
    float* out      = (float*)d_out;

    const int GRID = R_BLK + C_BLK + M_BLK;   // 2432 blocks

    for (int i = 0; i < NCHNK + 2; i++) {
        int br = (i < NCHNK)              ? i * CHUNK       : -1;
        int bc = (i >= 1 && i <= NCHNK)   ? (i - 1) * CHUNK : -1;
        int bm = (i >= 2)                 ? (i - 2) * CHUNK : -1;
        fused_kernel<<<GRID, 256>>>(x, wt, out, br, bc, bm);
    }
}